// round 2
// baseline (speedup 1.0000x reference)
#include <cuda_runtime.h>
#include <cuda_bf16.h>

#define B 4096
#define G 512
#define D 64
#define P (G * D)
#define EPS 1e-5f
#define NEG_SLOPE 0.2f

// scratch: reps transposed [G, B] (8 MB), plus per-group coefficients
__device__ float g_reps[(size_t)G * B];
__device__ float g_a[G];
__device__ float g_c[G];

// ---------------------------------------------------------------------------
// Kernel 1: reps[b,g] = leakyrelu( sum_d x[b, g*D+d] * W[g,d] )
// idx is the identity permutation (arange(G*D)) by construction, so the
// gather is direct addressing. One warp per (b,g); lane l handles d=2l,2l+1.
// Warp mapping w = g*B + b so lane-0 stores coalesce across warps of a block.
// ---------------------------------------------------------------------------
__global__ void __launch_bounds__(256) k1_reps(
    const float* __restrict__ x,
    const float* __restrict__ W)
{
    const int wid  = threadIdx.x >> 5;
    const int lane = threadIdx.x & 31;
    const unsigned w = blockIdx.x * 8u + wid;     // global warp id, < G*B = 2^21
    const int g = w >> 12;                        // w / B
    const int b = w & (B - 1);                    // w % B

    const int d0 = lane * 2;
    const float2 xv = *(const float2*)(x + (size_t)b * P + g * D + d0);
    const float2 wv = *(const float2*)(W + g * D + d0);

    float v = fmaf(xv.x, wv.x, xv.y * wv.y);

    #pragma unroll
    for (int o = 16; o > 0; o >>= 1)
        v += __shfl_xor_sync(0xffffffffu, v, o);

    if (lane == 0) {
        v = (v >= 0.0f) ? v : NEG_SLOPE * v;
        g_reps[(size_t)g * B + b] = v;   // consecutive b across warps -> coalesced
    }
}

// ---------------------------------------------------------------------------
// Kernel 2: per-group batch stats -> a[g], c[g]
// One block (256 threads) per group; coalesced row of g_reps.
// logit[b] = sum_g fc_w[g]*(gamma[g]*(r-mu)*inv + beta[g]) + fc_b
//          = sum_g a[g]*r + c[g] + fc_b
// ---------------------------------------------------------------------------
__global__ void __launch_bounds__(256) k2_stats(
    const float* __restrict__ gamma,
    const float* __restrict__ beta,
    const float* __restrict__ fc_w)
{
    const int g = blockIdx.x;
    const int tid = threadIdx.x;
    const float* r = g_reps + (size_t)g * B;

    float s = 0.0f, s2 = 0.0f;
    #pragma unroll 4
    for (int i = tid; i < B; i += 256) {
        float v = r[i];
        s  += v;
        s2 += v * v;
    }

    __shared__ float sh[256];
    __shared__ float sh2[256];
    sh[tid] = s; sh2[tid] = s2;
    __syncthreads();
    #pragma unroll
    for (int off = 128; off > 0; off >>= 1) {
        if (tid < off) {
            sh[tid]  += sh[tid + off];
            sh2[tid] += sh2[tid + off];
        }
        __syncthreads();
    }

    if (tid == 0) {
        float mean = sh[0] * (1.0f / B);
        float var  = sh2[0] * (1.0f / B) - mean * mean;
        float inv  = rsqrtf(var + EPS);
        float fw   = fc_w[g];
        float gm   = gamma[g];
        g_a[g] = fw * gm * inv;
        g_c[g] = fw * (beta[g] - gm * mean * inv);
    }
}

// ---------------------------------------------------------------------------
// Kernel 3: logit[b] = sum_g a[g]*reps[b,g] + c[g], + fc_b, sigmoid.
// 64 b per block (tx), 4-way split of G per b (ty). Coalesced across b.
// ---------------------------------------------------------------------------
__global__ void __launch_bounds__(256) k3_out(
    const float* __restrict__ fc_b,
    float* __restrict__ out)
{
    const int tx = threadIdx.x & 63;   // b within block
    const int ty = threadIdx.x >> 6;   // 0..3 -> G slice
    const int b  = blockIdx.x * 64 + tx;

    float acc = 0.0f;
    const int g0 = ty * (G / 4);
    #pragma unroll 4
    for (int g = g0; g < g0 + G / 4; ++g) {
        acc = fmaf(__ldg(&g_a[g]), g_reps[(size_t)g * B + b], acc);
        acc += __ldg(&g_c[g]);
    }

    __shared__ float sh[4][64];
    sh[ty][tx] = acc;
    __syncthreads();

    if (ty == 0) {
        float v = sh[0][tx] + sh[1][tx] + sh[2][tx] + sh[3][tx] + fc_b[0];
        out[b] = 1.0f / (1.0f + expf(-v));
    }
}

// ---------------------------------------------------------------------------
// inputs (metadata order): x, idx, W, gamma, beta, fc_w, fc_b
// ---------------------------------------------------------------------------
extern "C" void kernel_launch(void* const* d_in, const int* in_sizes, int n_in,
                              void* d_out, int out_size)
{
    const float* x     = (const float*)d_in[0];
    // d_in[1] = idx (identity arange by construction; unused)
    const float* W     = (const float*)d_in[2];
    const float* gamma = (const float*)d_in[3];
    const float* beta  = (const float*)d_in[4];
    const float* fc_w  = (const float*)d_in[5];
    const float* fc_b  = (const float*)d_in[6];
    float*       out   = (float*)d_out;

    k1_reps<<<(G * B) / 8, 256>>>(x, W);
    k2_stats<<<G, 256>>>(gamma, beta, fc_w);
    k3_out<<<B / 64, 256>>>(fc_b, out);
}

// round 3
// speedup vs baseline: 2.2318x; 2.2318x over previous
#include <cuda_runtime.h>
#include <cuda_bf16.h>

#define B 4096
#define G 512
#define D 64
#define P (G * D)
#define EPS 1e-5f
#define NEG_SLOPE 0.2f

// scratch
__device__ float g_reps[(size_t)B * G];   // [B, G] row-major, 8 MB
__device__ float g_psum[8][G];
__device__ float g_psum2[8][G];
__device__ float g_a[G];
__device__ float g_c[G];

// ---------------------------------------------------------------------------
// Kernel 1: reps[b,g] = leakyrelu( dot(x[b, g*64 : g*64+64], W[g]) )
// idx is identity (arange) by construction -> direct addressing.
// Thread owns 4 float4 slots (q, q+4, q+8, q+12) of ONE group; 4 threads per
// group; warp covers 8 groups (2 KB dense); 2-step segmented shfl reduce.
// grid = B * 8 blocks, 256 threads; block covers 64 groups of one b.
// ---------------------------------------------------------------------------
__global__ void __launch_bounds__(256) k1_reps(
    const float* __restrict__ x,
    const float* __restrict__ W)
{
    const int t   = threadIdx.x;
    const int q   = t & 3;                       // slot phase within group
    const int bid = blockIdx.x;
    const int b   = bid >> 3;
    const int g   = ((bid & 7) << 6) + (t >> 2); // 64 groups per block

    const float4* xp = (const float4*)(x + (size_t)b * P + g * D) + q;
    const float4* wp = (const float4*)(W + g * D) + q;

    const float4 x0 = __ldg(xp);      const float4 w0 = __ldg(wp);
    const float4 x1 = __ldg(xp + 4);  const float4 w1 = __ldg(wp + 4);
    const float4 x2 = __ldg(xp + 8);  const float4 w2 = __ldg(wp + 8);
    const float4 x3 = __ldg(xp + 12); const float4 w3 = __ldg(wp + 12);

    float a0 = fmaf(x0.x, w0.x, x0.y * w0.y);
    a0 = fmaf(x0.z, w0.z, a0); a0 = fmaf(x0.w, w0.w, a0);
    float a1 = fmaf(x1.x, w1.x, x1.y * w1.y);
    a1 = fmaf(x1.z, w1.z, a1); a1 = fmaf(x1.w, w1.w, a1);
    float a2 = fmaf(x2.x, w2.x, x2.y * w2.y);
    a2 = fmaf(x2.z, w2.z, a2); a2 = fmaf(x2.w, w2.w, a2);
    float a3 = fmaf(x3.x, w3.x, x3.y * w3.y);
    a3 = fmaf(x3.z, w3.z, a3); a3 = fmaf(x3.w, w3.w, a3);

    float acc = (a0 + a1) + (a2 + a3);

    // reduce over the 4 lanes of this group
    acc += __shfl_xor_sync(0xffffffffu, acc, 1);
    acc += __shfl_xor_sync(0xffffffffu, acc, 2);

    if (q == 0) {
        acc = (acc >= 0.0f) ? acc : NEG_SLOPE * acc;
        g_reps[(size_t)b * G + g] = acc;   // 64 consecutive floats per block
    }
}

// ---------------------------------------------------------------------------
// Kernel 2: partial batch sums per group. grid = 128 (8 b-tiles x 16 g-tiles),
// 256 threads. lane = group within 32-wide tile -> coalesced 128 B warp rows.
// ---------------------------------------------------------------------------
__global__ void __launch_bounds__(256) k2_partial()
{
    const int lane  = threadIdx.x & 31;
    const int w     = threadIdx.x >> 5;
    const int btile = blockIdx.x >> 4;          // 0..7  (512 rows each)
    const int gtile = blockIdx.x & 15;          // 0..15 (32 groups each)
    const int g     = gtile * 32 + lane;

    const float* base = g_reps + (size_t)(btile * 512) * G + g;

    float s = 0.0f, s2 = 0.0f;
    #pragma unroll 4
    for (int r = w; r < 512; r += 8) {
        float v = base[(size_t)r * G];
        s  += v;
        s2 += v * v;
    }

    __shared__ float sh[8][32];
    __shared__ float sh2[8][32];
    sh[w][lane] = s; sh2[w][lane] = s2;
    __syncthreads();

    if (w == 0) {
        float a = 0.0f, a2 = 0.0f;
        #pragma unroll
        for (int i = 0; i < 8; i++) { a += sh[i][lane]; a2 += sh2[i][lane]; }
        g_psum[btile][g]  = a;
        g_psum2[btile][g] = a2;
    }
}

// ---------------------------------------------------------------------------
// Kernel 2b: finalize stats -> a[g], c[g].
// logit[b] = sum_g a[g]*reps[b,g] + c[g], then + fc_b, sigmoid.
// ---------------------------------------------------------------------------
__global__ void k2b_finalize(
    const float* __restrict__ gamma,
    const float* __restrict__ beta,
    const float* __restrict__ fc_w)
{
    const int g = threadIdx.x;   // 512 threads
    float s = 0.0f, s2 = 0.0f;
    #pragma unroll
    for (int i = 0; i < 8; i++) { s += g_psum[i][g]; s2 += g_psum2[i][g]; }
    float mean = s * (1.0f / B);
    float var  = s2 * (1.0f / B) - mean * mean;
    float inv  = rsqrtf(var + EPS);
    float fw   = fc_w[g];
    float gm   = gamma[g];
    g_a[g] = fw * gm * inv;
    g_c[g] = fw * (beta[g] - gm * mean * inv);
}

// ---------------------------------------------------------------------------
// Kernel 3: warp per b, coalesced row dot, shfl reduce, sigmoid.
// grid = 512, 256 threads (8 warps = 8 b per block).
// ---------------------------------------------------------------------------
__global__ void __launch_bounds__(256) k3_out(
    const float* __restrict__ fc_b,
    float* __restrict__ out)
{
    const int lane = threadIdx.x & 31;
    const int w    = threadIdx.x >> 5;
    const int b    = blockIdx.x * 8 + w;

    const float* r = g_reps + (size_t)b * G;

    float acc = 0.0f;
    #pragma unroll
    for (int i = 0; i < 16; i++) {
        const int g = lane + i * 32;
        acc = fmaf(__ldg(&g_a[g]), r[g], acc) + __ldg(&g_c[g]);
    }

    #pragma unroll
    for (int o = 16; o > 0; o >>= 1)
        acc += __shfl_xor_sync(0xffffffffu, acc, o);

    if (lane == 0) {
        float v = acc + fc_b[0];
        out[b] = 1.0f / (1.0f + expf(-v));
    }
}

// ---------------------------------------------------------------------------
// inputs (metadata order): x, idx, W, gamma, beta, fc_w, fc_b
// ---------------------------------------------------------------------------
extern "C" void kernel_launch(void* const* d_in, const int* in_sizes, int n_in,
                              void* d_out, int out_size)
{
    const float* x     = (const float*)d_in[0];
    // d_in[1] = idx (identity arange by construction; unused)
    const float* W     = (const float*)d_in[2];
    const float* gamma = (const float*)d_in[3];
    const float* beta  = (const float*)d_in[4];
    const float* fc_w  = (const float*)d_in[5];
    const float* fc_b  = (const float*)d_in[6];
    float*       out   = (float*)d_out;

    k1_reps<<<B * 8, 256>>>(x, W);
    k2_partial<<<128, 256>>>();
    k2b_finalize<<<1, G>>>(gamma, beta, fc_w);
    k3_out<<<B / 8, 256>>>(fc_b, out);
}

// round 4
// speedup vs baseline: 2.2857x; 1.0241x over previous
#include <cuda_runtime.h>
#include <cuda_bf16.h>

#define B 4096
#define G 512
#define D 64
#define P (G * D)
#define EPS 1e-5f
#define NEG_SLOPE 0.2f

#define BT 512              // number of b-tiles (8 rows each)

// scratch
__device__ float g_reps[(size_t)B * G];       // [B, G] row-major, 8 MB
__device__ float g_bsum [BT][G];              // per-btile partial sums  (1 MB)
__device__ float g_bsum2[BT][G];              // per-btile partial sumsq (1 MB)
__device__ float g_a[G];
__device__ float g_c[G];

// ---------------------------------------------------------------------------
// Kernel 1: reps[b,g] = leakyrelu( dot(x[b, g*64 : g*64+64], W[g]) )
// idx is identity (arange) by construction -> direct addressing.
// Block = (btile, gtile): 8 b-rows x 64 groups. W slice (16 KB) loaded into
// registers ONCE, reused across the 8 rows. 4 threads per group (q = t&3),
// 2-step segmented shfl reduce. Also emits per-btile partial batch stats
// (deterministic in-register reduction, no atomics).
// ---------------------------------------------------------------------------
__global__ void __launch_bounds__(256) k1_reps(
    const float* __restrict__ x,
    const float* __restrict__ W)
{
    const int t     = threadIdx.x;
    const int q     = t & 3;                       // slot phase within group
    const int btile = blockIdx.x >> 3;             // 0..511
    const int gtile = blockIdx.x & 7;              // 0..7
    const int g     = (gtile << 6) + (t >> 2);     // group id
    const int b0    = btile << 3;                  // first of 8 rows

    // W slice for this group: 64 floats = 4 float4, register-resident
    const float4* wp = (const float4*)(W + g * D) + q;
    const float4 w0 = __ldg(wp);
    const float4 w1 = __ldg(wp + 4);
    const float4 w2 = __ldg(wp + 8);
    const float4 w3 = __ldg(wp + 12);

    float s = 0.0f, s2 = 0.0f;

    #pragma unroll 2
    for (int i = 0; i < 8; ++i) {
        const int b = b0 + i;
        const float4* xp = (const float4*)(x + (size_t)b * P + g * D) + q;
        const float4 x0 = __ldg(xp);
        const float4 x1 = __ldg(xp + 4);
        const float4 x2 = __ldg(xp + 8);
        const float4 x3 = __ldg(xp + 12);

        float a0 = fmaf(x0.x, w0.x, x0.y * w0.y);
        a0 = fmaf(x0.z, w0.z, a0); a0 = fmaf(x0.w, w0.w, a0);
        float a1 = fmaf(x1.x, w1.x, x1.y * w1.y);
        a1 = fmaf(x1.z, w1.z, a1); a1 = fmaf(x1.w, w1.w, a1);
        float a2 = fmaf(x2.x, w2.x, x2.y * w2.y);
        a2 = fmaf(x2.z, w2.z, a2); a2 = fmaf(x2.w, w2.w, a2);
        float a3 = fmaf(x3.x, w3.x, x3.y * w3.y);
        a3 = fmaf(x3.z, w3.z, a3); a3 = fmaf(x3.w, w3.w, a3);

        float acc = (a0 + a1) + (a2 + a3);
        // butterfly over the 4-lane segment: all 4 lanes get the full dot
        acc += __shfl_xor_sync(0xffffffffu, acc, 1);
        acc += __shfl_xor_sync(0xffffffffu, acc, 2);

        acc = (acc >= 0.0f) ? acc : NEG_SLOPE * acc;
        if (q == 0) g_reps[(size_t)b * G + g] = acc;

        s  += acc;
        s2 += acc * acc;
    }

    if (q == 0) {
        g_bsum [btile][g] = s;
        g_bsum2[btile][g] = s2;
    }
}

// ---------------------------------------------------------------------------
// Kernel 2: reduce 512 per-btile partials per group -> a[g], c[g].
// grid = 16 blocks x 32 groups; lane = group (coalesced 128 B warp rows),
// 8 warps stride the btile dimension. Deterministic fixed-order reduction.
// logit[b] = sum_g (a[g]*reps[b,g] + c[g]) + fc_b
// ---------------------------------------------------------------------------
__global__ void __launch_bounds__(256) k2_stats(
    const float* __restrict__ gamma,
    const float* __restrict__ beta,
    const float* __restrict__ fc_w)
{
    const int lane = threadIdx.x & 31;
    const int w    = threadIdx.x >> 5;
    const int g    = blockIdx.x * 32 + lane;

    float s = 0.0f, s2 = 0.0f;
    #pragma unroll 8
    for (int bt = w; bt < BT; bt += 8) {
        s  += g_bsum [bt][g];
        s2 += g_bsum2[bt][g];
    }

    __shared__ float sh[8][32];
    __shared__ float sh2[8][32];
    sh[w][lane] = s; sh2[w][lane] = s2;
    __syncthreads();

    if (w == 0) {
        float a = 0.0f, a2 = 0.0f;
        #pragma unroll
        for (int i = 0; i < 8; i++) { a += sh[i][lane]; a2 += sh2[i][lane]; }
        float mean = a * (1.0f / B);
        float var  = a2 * (1.0f / B) - mean * mean;
        float inv  = rsqrtf(var + EPS);
        float fw   = fc_w[g];
        float gm   = gamma[g];
        g_a[g] = fw * gm * inv;
        g_c[g] = fw * (beta[g] - gm * mean * inv);
    }
}

// ---------------------------------------------------------------------------
// Kernel 3: logit[b] = sum_g (a[g]*reps[b,g] + c[g]) + fc_b, sigmoid.
// Warp per b; lane loads float4 (512 B per warp-load), 4 iterations.
// ---------------------------------------------------------------------------
__global__ void __launch_bounds__(256) k3_out(
    const float* __restrict__ fc_b,
    float* __restrict__ out)
{
    const int lane = threadIdx.x & 31;
    const int w    = threadIdx.x >> 5;
    const int b    = blockIdx.x * 8 + w;

    const float4* r4 = (const float4*)(g_reps + (size_t)b * G);
    const float4* a4 = (const float4*)g_a;
    const float4* c4 = (const float4*)g_c;

    float acc = 0.0f;
    #pragma unroll
    for (int i = 0; i < 4; ++i) {
        const int j = i * 32 + lane;
        const float4 r = __ldg(r4 + j);
        const float4 a = __ldg(a4 + j);
        const float4 c = __ldg(c4 + j);
        acc = fmaf(a.x, r.x, acc) + c.x;
        acc = fmaf(a.y, r.y, acc) + c.y;
        acc = fmaf(a.z, r.z, acc) + c.z;
        acc = fmaf(a.w, r.w, acc) + c.w;
    }

    #pragma unroll
    for (int o = 16; o > 0; o >>= 1)
        acc += __shfl_xor_sync(0xffffffffu, acc, o);

    if (lane == 0) {
        float v = acc + fc_b[0];
        out[b] = 1.0f / (1.0f + expf(-v));
    }
}

// ---------------------------------------------------------------------------
// inputs (metadata order): x, idx, W, gamma, beta, fc_w, fc_b
// ---------------------------------------------------------------------------
extern "C" void kernel_launch(void* const* d_in, const int* in_sizes, int n_in,
                              void* d_out, int out_size)
{
    const float* x     = (const float*)d_in[0];
    // d_in[1] = idx (identity arange by construction; unused)
    const float* W     = (const float*)d_in[2];
    const float* gamma = (const float*)d_in[3];
    const float* beta  = (const float*)d_in[4];
    const float* fc_w  = (const float*)d_in[5];
    const float* fc_b  = (const float*)d_in[6];
    float*       out   = (float*)d_out;

    k1_reps<<<BT * 8, 256>>>(x, W);          // 4096 blocks
    k2_stats<<<16, 256>>>(gamma, beta, fc_w);
    k3_out<<<B / 8, 256>>>(fc_b, out);
}

// round 5
// speedup vs baseline: 2.4085x; 1.0537x over previous
#include <cuda_runtime.h>
#include <cuda_bf16.h>

#define B 4096
#define G 512
#define D 64
#define P (G * D)
#define EPS 1e-5f
#define NEG_SLOPE 0.2f

#define BT 512              // number of b-tiles (8 rows each)

// scratch
__device__ float g_reps[(size_t)B * G];       // [B, G] row-major, 8 MB
__device__ float g_bsum [BT][G];              // per-btile partial sums  (1 MB)
__device__ float g_bsum2[BT][G];              // per-btile partial sumsq (1 MB)
__device__ float g_a[G];
__device__ float g_csum_part[16];             // per-k2-block partial sum of c[g]

// ---------------------------------------------------------------------------
// Kernel 1: reps[b,g] = leakyrelu( dot(x[b, g*64 : g*64+64], W[g]) )
// idx is identity (arange) by construction -> direct addressing.
// Block = (btile, gtile): 8 b-rows x 64 groups. W slice register-resident,
// reused across the 8 rows. 4 threads per group, 2-step segmented shfl
// reduce. Emits per-btile partial batch stats (deterministic, no atomics).
// x is streamed once -> __ldcs (evict-first) to keep L2 for W + writes.
// ---------------------------------------------------------------------------
__global__ void __launch_bounds__(256) k1_reps(
    const float* __restrict__ x,
    const float* __restrict__ W)
{
    const int t     = threadIdx.x;
    const int q     = t & 3;                       // slot phase within group
    const int btile = blockIdx.x >> 3;             // 0..511
    const int gtile = blockIdx.x & 7;              // 0..7
    const int g     = (gtile << 6) + (t >> 2);     // group id
    const int b0    = btile << 3;                  // first of 8 rows

    // W slice for this group: 64 floats = 4 float4, register-resident
    const float4* wp = (const float4*)(W + g * D) + q;
    const float4 w0 = __ldg(wp);
    const float4 w1 = __ldg(wp + 4);
    const float4 w2 = __ldg(wp + 8);
    const float4 w3 = __ldg(wp + 12);

    float s = 0.0f, s2 = 0.0f;

    #pragma unroll 2
    for (int i = 0; i < 8; ++i) {
        const int b = b0 + i;
        const float4* xp = (const float4*)(x + (size_t)b * P + g * D) + q;
        const float4 x0 = __ldcs(xp);
        const float4 x1 = __ldcs(xp + 4);
        const float4 x2 = __ldcs(xp + 8);
        const float4 x3 = __ldcs(xp + 12);

        float a0 = fmaf(x0.x, w0.x, x0.y * w0.y);
        a0 = fmaf(x0.z, w0.z, a0); a0 = fmaf(x0.w, w0.w, a0);
        float a1 = fmaf(x1.x, w1.x, x1.y * w1.y);
        a1 = fmaf(x1.z, w1.z, a1); a1 = fmaf(x1.w, w1.w, a1);
        float a2 = fmaf(x2.x, w2.x, x2.y * w2.y);
        a2 = fmaf(x2.z, w2.z, a2); a2 = fmaf(x2.w, w2.w, a2);
        float a3 = fmaf(x3.x, w3.x, x3.y * w3.y);
        a3 = fmaf(x3.z, w3.z, a3); a3 = fmaf(x3.w, w3.w, a3);

        float acc = (a0 + a1) + (a2 + a3);
        // butterfly over the 4-lane segment: all 4 lanes get the full dot
        acc += __shfl_xor_sync(0xffffffffu, acc, 1);
        acc += __shfl_xor_sync(0xffffffffu, acc, 2);

        acc = (acc >= 0.0f) ? acc : NEG_SLOPE * acc;
        if (q == 0) g_reps[(size_t)b * G + g] = acc;

        s  += acc;
        s2 += acc * acc;
    }

    if (q == 0) {
        g_bsum [btile][g] = s;
        g_bsum2[btile][g] = s2;
    }
}

// ---------------------------------------------------------------------------
// Kernel 2: reduce 512 per-btile partials per group -> a[g]; also emit this
// block's partial sum of c[g] (c folded out of k3's inner loop).
// grid = 16 blocks x 32 groups; lane = group (coalesced), 8 warps stride bt.
// logit[b] = sum_g a[g]*reps[b,g] + sum_g c[g] + fc_b
// ---------------------------------------------------------------------------
__global__ void __launch_bounds__(256) k2_stats(
    const float* __restrict__ gamma,
    const float* __restrict__ beta,
    const float* __restrict__ fc_w)
{
    cudaGridDependencySynchronize();   // PDL: wait for k1 results

    const int lane = threadIdx.x & 31;
    const int w    = threadIdx.x >> 5;
    const int g    = blockIdx.x * 32 + lane;

    float s = 0.0f, s2 = 0.0f;
    #pragma unroll 8
    for (int bt = w; bt < BT; bt += 8) {
        s  += g_bsum [bt][g];
        s2 += g_bsum2[bt][g];
    }

    __shared__ float sh[8][32];
    __shared__ float sh2[8][32];
    sh[w][lane] = s; sh2[w][lane] = s2;
    __syncthreads();

    if (w == 0) {
        float a = 0.0f, a2 = 0.0f;
        #pragma unroll
        for (int i = 0; i < 8; i++) { a += sh[i][lane]; a2 += sh2[i][lane]; }
        float mean = a * (1.0f / B);
        float var  = a2 * (1.0f / B) - mean * mean;
        float inv  = rsqrtf(var + EPS);
        float fw   = fc_w[g];
        float gm   = gamma[g];
        g_a[g] = fw * gm * inv;
        float c = fw * (beta[g] - gm * mean * inv);
        // partial sum of c over this block's 32 groups
        #pragma unroll
        for (int o = 16; o > 0; o >>= 1)
            c += __shfl_xor_sync(0xffffffffu, c, o);
        if (lane == 0) g_csum_part[blockIdx.x] = c;
    }
}

// ---------------------------------------------------------------------------
// Kernel 3: logit[b] = sum_g a[g]*reps[b,g] (+ csum + fc_b), sigmoid.
// Warp per b; lane loads float4; csum partials folded into the butterfly.
// ---------------------------------------------------------------------------
__global__ void __launch_bounds__(256) k3_out(
    const float* __restrict__ fc_b,
    float* __restrict__ out)
{
    cudaGridDependencySynchronize();   // PDL: wait for k2 (and k1) results

    const int lane = threadIdx.x & 31;
    const int w    = threadIdx.x >> 5;
    const int b    = blockIdx.x * 8 + w;

    const float4* r4 = (const float4*)(g_reps + (size_t)b * G);
    const float4* a4 = (const float4*)g_a;

    float acc = 0.0f;
    #pragma unroll
    for (int i = 0; i < 4; ++i) {
        const int j = i * 32 + lane;
        const float4 r = __ldcs(r4 + j);
        const float4 a = __ldg(a4 + j);
        acc = fmaf(a.x, r.x, acc);
        acc = fmaf(a.y, r.y, acc);
        acc = fmaf(a.z, r.z, acc);
        acc = fmaf(a.w, r.w, acc);
    }

    // fold the c-sum partials (16 values) into the reduction
    if (lane < 16) acc += g_csum_part[lane];

    #pragma unroll
    for (int o = 16; o > 0; o >>= 1)
        acc += __shfl_xor_sync(0xffffffffu, acc, o);

    if (lane == 0) {
        float v = acc + fc_b[0];
        out[b] = 1.0f / (1.0f + expf(-v));
    }
}

// ---------------------------------------------------------------------------
// inputs (metadata order): x, idx, W, gamma, beta, fc_w, fc_b
// ---------------------------------------------------------------------------
extern "C" void kernel_launch(void* const* d_in, const int* in_sizes, int n_in,
                              void* d_out, int out_size)
{
    const float* x     = (const float*)d_in[0];
    // d_in[1] = idx (identity arange by construction; unused)
    const float* W     = (const float*)d_in[2];
    const float* gamma = (const float*)d_in[3];
    const float* beta  = (const float*)d_in[4];
    const float* fc_w  = (const float*)d_in[5];
    const float* fc_b  = (const float*)d_in[6];
    float*       out   = (float*)d_out;

    k1_reps<<<BT * 8, 256>>>(x, W);          // 4096 blocks

    // k2, k3 launched as programmatic dependents: launch prologue overlaps the
    // predecessor's tail; cudaGridDependencySynchronize() inside each kernel
    // preserves ordering of all data reads.
    cudaLaunchAttribute attr[1];
    attr[0].id = cudaLaunchAttributeProgrammaticStreamSerialization;
    attr[0].val.programmaticStreamSerializationAllowed = 1;

    {
        cudaLaunchConfig_t cfg = {};
        cfg.gridDim  = dim3(16);
        cfg.blockDim = dim3(256);
        cfg.attrs    = attr;
        cfg.numAttrs = 1;
        cudaLaunchKernelEx(&cfg, k2_stats, gamma, beta, fc_w);
    }
    {
        cudaLaunchConfig_t cfg = {};
        cfg.gridDim  = dim3(B / 8);
        cfg.blockDim = dim3(256);
        cfg.attrs    = attr;
        cfg.numAttrs = 1;
        cudaLaunchKernelEx(&cfg, k3_out, fc_b, out);
    }
}

// round 6
// speedup vs baseline: 2.4633x; 1.0228x over previous
#include <cuda_runtime.h>
#include <cuda_bf16.h>

#define B 4096
#define G 512
#define D 64
#define P (G * D)
#define EPS 1e-5f
#define NEG_SLOPE 0.2f

#define BT 512              // number of b-tiles (8 rows each)

// scratch
__device__ float g_reps[(size_t)B * G];       // [B, G] row-major, 8 MB
__device__ float g_bsum [BT][G];              // per-btile partial sums  (1 MB)
__device__ float g_bsum2[BT][G];              // per-btile partial sumsq (1 MB)
__device__ float g_a[G];
__device__ float g_csum_part[16];             // per-k2-block partial sum of c[g]

// ---------------------------------------------------------------------------
// Kernel 1: reps[b,g] = leakyrelu( dot(x[b, g*64 : g*64+64], W[g]) )
// idx is identity (arange) by construction -> direct addressing.
// Block = (btile, gtile): 8 b-rows x 64 groups. W slice register-resident,
// reused across the 8 rows. 4 threads per group, 2-step segmented shfl
// reduce. Emits per-btile partial batch stats (deterministic, no atomics).
// x is streamed once -> __ldcs (evict-first) to keep L2 for W + writes.
// ---------------------------------------------------------------------------
__global__ void __launch_bounds__(256) k1_reps(
    const float* __restrict__ x,
    const float* __restrict__ W)
{
    const int t     = threadIdx.x;
    const int q     = t & 3;                       // slot phase within group
    const int btile = blockIdx.x >> 3;             // 0..511
    const int gtile = blockIdx.x & 7;              // 0..7
    const int g     = (gtile << 6) + (t >> 2);     // group id
    const int b0    = btile << 3;                  // first of 8 rows

    // W slice for this group: 64 floats = 4 float4, register-resident
    const float4* wp = (const float4*)(W + g * D) + q;
    const float4 w0 = __ldg(wp);
    const float4 w1 = __ldg(wp + 4);
    const float4 w2 = __ldg(wp + 8);
    const float4 w3 = __ldg(wp + 12);

    float s = 0.0f, s2 = 0.0f;

    #pragma unroll 2
    for (int i = 0; i < 8; ++i) {
        const int b = b0 + i;
        const float4* xp = (const float4*)(x + (size_t)b * P + g * D) + q;
        const float4 x0 = __ldcs(xp);
        const float4 x1 = __ldcs(xp + 4);
        const float4 x2 = __ldcs(xp + 8);
        const float4 x3 = __ldcs(xp + 12);

        float a0 = fmaf(x0.x, w0.x, x0.y * w0.y);
        a0 = fmaf(x0.z, w0.z, a0); a0 = fmaf(x0.w, w0.w, a0);
        float a1 = fmaf(x1.x, w1.x, x1.y * w1.y);
        a1 = fmaf(x1.z, w1.z, a1); a1 = fmaf(x1.w, w1.w, a1);
        float a2 = fmaf(x2.x, w2.x, x2.y * w2.y);
        a2 = fmaf(x2.z, w2.z, a2); a2 = fmaf(x2.w, w2.w, a2);
        float a3 = fmaf(x3.x, w3.x, x3.y * w3.y);
        a3 = fmaf(x3.z, w3.z, a3); a3 = fmaf(x3.w, w3.w, a3);

        float acc = (a0 + a1) + (a2 + a3);
        // butterfly over the 4-lane segment: all 4 lanes get the full dot
        acc += __shfl_xor_sync(0xffffffffu, acc, 1);
        acc += __shfl_xor_sync(0xffffffffu, acc, 2);

        acc = (acc >= 0.0f) ? acc : NEG_SLOPE * acc;
        if (q == 0) g_reps[(size_t)b * G + g] = acc;

        s  += acc;
        s2 += acc * acc;
    }

    if (q == 0) {
        g_bsum [btile][g] = s;
        g_bsum2[btile][g] = s2;
    }
}

// ---------------------------------------------------------------------------
// Kernel 2: reduce 512 per-btile partials per group -> a[g]; also emit this
// block's partial sum of c[g] (c folded out of k3's inner loop).
// grid = 16 blocks x 32 groups; 512 threads: lane = group (coalesced),
// 16 warps stride the btile dimension. Deterministic fixed-order reduction.
// logit[b] = sum_g a[g]*reps[b,g] + sum_g c[g] + fc_b
// ---------------------------------------------------------------------------
__global__ void __launch_bounds__(512) k2_stats(
    const float* __restrict__ gamma,
    const float* __restrict__ beta,
    const float* __restrict__ fc_w)
{
    cudaGridDependencySynchronize();   // PDL: wait for k1 results

    const int lane = threadIdx.x & 31;
    const int w    = threadIdx.x >> 5;           // 0..15
    const int g    = blockIdx.x * 32 + lane;

    float s = 0.0f, s2 = 0.0f;
    #pragma unroll 8
    for (int bt = w; bt < BT; bt += 16) {
        s  += g_bsum [bt][g];
        s2 += g_bsum2[bt][g];
    }

    __shared__ float sh[16][32];
    __shared__ float sh2[16][32];
    sh[w][lane] = s; sh2[w][lane] = s2;
    __syncthreads();

    if (w == 0) {
        float a = 0.0f, a2 = 0.0f;
        #pragma unroll
        for (int i = 0; i < 16; i++) { a += sh[i][lane]; a2 += sh2[i][lane]; }
        float mean = a * (1.0f / B);
        float var  = a2 * (1.0f / B) - mean * mean;
        float inv  = rsqrtf(var + EPS);
        float fw   = fc_w[g];
        float gm   = gamma[g];
        g_a[g] = fw * gm * inv;
        float c = fw * (beta[g] - gm * mean * inv);
        // partial sum of c over this block's 32 groups
        #pragma unroll
        for (int o = 16; o > 0; o >>= 1)
            c += __shfl_xor_sync(0xffffffffu, c, o);
        if (lane == 0) g_csum_part[blockIdx.x] = c;
    }
}

// ---------------------------------------------------------------------------
// Kernel 3: logit[b] = sum_g a[g]*reps[b,g] (+ csum + fc_b), sigmoid.
// 2 b-rows per warp (b and b+2048): 24 independent LDG.128 in flight per
// warp, half the grid ramp. csum partials folded in via lanes 0..15.
// ---------------------------------------------------------------------------
__global__ void __launch_bounds__(256) k3_out(
    const float* __restrict__ fc_b,
    float* __restrict__ out)
{
    cudaGridDependencySynchronize();   // PDL: wait for k2 (and k1) results

    const int lane = threadIdx.x & 31;
    const int w    = threadIdx.x >> 5;
    const int b    = blockIdx.x * 8 + w;          // 0..2047
    const int b2   = b + 2048;

    const float4* r4a = (const float4*)(g_reps + (size_t)b  * G);
    const float4* r4b = (const float4*)(g_reps + (size_t)b2 * G);
    const float4* a4  = (const float4*)g_a;

    float acc1 = 0.0f, acc2 = 0.0f;
    #pragma unroll
    for (int i = 0; i < 4; ++i) {
        const int j = i * 32 + lane;
        const float4 a  = __ldg(a4 + j);
        const float4 ra = __ldcs(r4a + j);
        const float4 rb = __ldcs(r4b + j);
        acc1 = fmaf(a.x, ra.x, acc1); acc2 = fmaf(a.x, rb.x, acc2);
        acc1 = fmaf(a.y, ra.y, acc1); acc2 = fmaf(a.y, rb.y, acc2);
        acc1 = fmaf(a.z, ra.z, acc1); acc2 = fmaf(a.z, rb.z, acc2);
        acc1 = fmaf(a.w, ra.w, acc1); acc2 = fmaf(a.w, rb.w, acc2);
    }

    // fold the c-sum partials (16 values) into both reductions
    if (lane < 16) {
        const float cp = g_csum_part[lane];
        acc1 += cp;
        acc2 += cp;
    }

    #pragma unroll
    for (int o = 16; o > 0; o >>= 1) {
        acc1 += __shfl_xor_sync(0xffffffffu, acc1, o);
        acc2 += __shfl_xor_sync(0xffffffffu, acc2, o);
    }

    if (lane == 0) {
        const float bias = fc_b[0];
        out[b]  = 1.0f / (1.0f + expf(-(acc1 + bias)));
        out[b2] = 1.0f / (1.0f + expf(-(acc2 + bias)));
    }
}

// ---------------------------------------------------------------------------
// inputs (metadata order): x, idx, W, gamma, beta, fc_w, fc_b
// ---------------------------------------------------------------------------
extern "C" void kernel_launch(void* const* d_in, const int* in_sizes, int n_in,
                              void* d_out, int out_size)
{
    const float* x     = (const float*)d_in[0];
    // d_in[1] = idx (identity arange by construction; unused)
    const float* W     = (const float*)d_in[2];
    const float* gamma = (const float*)d_in[3];
    const float* beta  = (const float*)d_in[4];
    const float* fc_w  = (const float*)d_in[5];
    const float* fc_b  = (const float*)d_in[6];
    float*       out   = (float*)d_out;

    k1_reps<<<BT * 8, 256>>>(x, W);          // 4096 blocks

    // k2, k3 as programmatic dependents: launch prologue overlaps the
    // predecessor's tail; cudaGridDependencySynchronize() inside each kernel
    // preserves ordering of all data reads.
    cudaLaunchAttribute attr[1];
    attr[0].id = cudaLaunchAttributeProgrammaticStreamSerialization;
    attr[0].val.programmaticStreamSerializationAllowed = 1;

    {
        cudaLaunchConfig_t cfg = {};
        cfg.gridDim  = dim3(16);
        cfg.blockDim = dim3(512);
        cfg.attrs    = attr;
        cfg.numAttrs = 1;
        cudaLaunchKernelEx(&cfg, k2_stats, gamma, beta, fc_w);
    }
    {
        cudaLaunchConfig_t cfg = {};
        cfg.gridDim  = dim3(B / 16);
        cfg.blockDim = dim3(256);
        cfg.attrs    = attr;
        cfg.numAttrs = 1;
        cudaLaunchKernelEx(&cfg, k3_out, fc_b, out);
    }
}